// round 16
// baseline (speedup 1.0000x reference)
#include <cuda_runtime.h>
#include <cuda_bf16.h>

#define NTOT (64*2048)
#define D    256
#define COND 64
#define NG   64
#define NPG  2048

typedef unsigned long long u64;
typedef unsigned int u32;

// ---------------- device scratch ----------------
__device__ float g_pooled[NG*128];    // atomic-accumulated (zeroed by main each run)
__device__ float g_u[NG*D];
__device__ float g_G[COND*COND];      // atomic-accumulated Gram (zeroed by main each run)
__device__ float g_s[NG*COND];        // atomic-accumulated per-graph col sums
__device__ float g_a[D];
__device__ float g_c[D];
__device__ uint4 g_WfragH[2048];
__device__ uint4 g_WfragL[2048];

extern __shared__ float dsm[];

// ---------------- f32x2 + misc helpers ----------------
__device__ __forceinline__ u64 fma2(u64 a, u64 b, u64 c){
    u64 d; asm("fma.rn.f32x2 %0, %1, %2, %3;" : "=l"(d) : "l"(a), "l"(b), "l"(c)); return d;
}
__device__ __forceinline__ u64 mul2(u64 a, u64 b){
    u64 d; asm("mul.rn.f32x2 %0, %1, %2;" : "=l"(d) : "l"(a), "l"(b)); return d;
}
__device__ __forceinline__ u64 add2(u64 a, u64 b){
    u64 d; asm("add.rn.f32x2 %0, %1, %2;" : "=l"(d) : "l"(a), "l"(b)); return d;
}
__device__ __forceinline__ u64 dup2(float v){
    u64 r; asm("mov.b64 %0, {%1, %1};" : "=l"(r) : "f"(v)); return r;
}
__device__ __forceinline__ u64 pk2(float x, float y){
    u64 r; asm("mov.b64 %0, {%1, %2};" : "=l"(r) : "f"(x), "f"(y)); return r;
}
__device__ __forceinline__ float2 upk2(u64 v){
    float2 f; asm("mov.b64 {%0, %1}, %2;" : "=f"(f.x), "=f"(f.y) : "l"(v)); return f;
}
__device__ __forceinline__ unsigned short bf16hi_us(float w){
    return __bfloat16_as_ushort(__float2bfloat16(w));
}
__device__ __forceinline__ unsigned short bf16lo_us(float w){
    float r = w - __bfloat162float(__float2bfloat16(w));
    return __bfloat16_as_ushort(__float2bfloat16(r));
}
__device__ __forceinline__ void cvt_hl(float2 v, u32& hi, u32& lo){
    __nv_bfloat162 h = __float22bfloat162_rn(v);
    float2 hf = __bfloat1622float2(h);
    __nv_bfloat162 l2 = __float22bfloat162_rn(make_float2(v.x - hf.x, v.y - hf.y));
    hi = *reinterpret_cast<u32*>(&h);
    lo = *reinterpret_cast<u32*>(&l2);
}
__device__ __forceinline__ void mma16816(float* c, const u32* a, u32 b0, u32 b1){
    asm("mma.sync.aligned.m16n8k16.row.col.f32.bf16.bf16.f32 "
        "{%0,%1,%2,%3}, {%4,%5,%6,%7}, {%8,%9}, {%0,%1,%2,%3};"
        : "+f"(c[0]), "+f"(c[1]), "+f"(c[2]), "+f"(c[3])
        : "r"(a[0]), "r"(a[1]), "r"(a[2]), "r"(a[3]), "r"(b0), "r"(b1));
}

// Packed tanh-form GELU using MUFU.TANH
__device__ __forceinline__ u64 gelu2t(u64 y2){
    u64 xx    = mul2(y2, y2);
    u64 inner = fma2(xx, dup2(0.044715f), dup2(1.0f));
    u64 arg   = mul2(mul2(y2, inner), dup2(0.79788456080286536f));
    float2 av = upk2(arg);
    float t0, t1;
    asm("tanh.approx.f32 %0, %1;" : "=f"(t0) : "f"(av.x));
    asm("tanh.approx.f32 %0, %1;" : "=f"(t1) : "f"(av.y));
    u64 half = fma2(pk2(t0, t1), dup2(0.5f), dup2(0.5f));
    return mul2(y2, half);
}

// ================= K0: prep — gram(0..511) + wfrag(512..519) + pool(520..2567) =================
// 16 KB static smem -> 8 blocks/SM. LPT: long gram blocks first.
__global__ void __launch_bounds__(256) prep_kernel(const float* __restrict__ x,
                                                   const float* __restrict__ cond,
                                                   const float* __restrict__ W1){
    __shared__ float tile[4096];   // 16 KB
    int blk = blockIdx.x, tid = threadIdx.x;

    if (blk < 512){
        // ---- gram: 512 blocks x 256 rows (4 sub-tiles of 64), atomics into g_G / g_s ----
        int gb = blk;
        int ti = tid >> 4, tj = tid & 15;
        int ri = ti*4, cj = tj*4;
        u64 acc[4][2];
        #pragma unroll
        for (int r = 0; r < 4; r++){ acc[r][0] = 0ull; acc[r][1] = 0ull; }
        float ssum = 0.0f;

        for (int sub = 0; sub < 4; sub++){
            size_t base = ((size_t)gb*256 + sub*64) * COND;
            for (int i = tid; i < 4096; i += 256) tile[i] = cond[base + i];
            __syncthreads();
            #pragma unroll 4
            for (int k = 0; k < 64; k++){
                float4 av = *(const float4*)(tile + k*64 + ri);
                u64 A0 = dup2(av.x), A1 = dup2(av.y), A2 = dup2(av.z), A3 = dup2(av.w);
                ulonglong2 bb = *(const ulonglong2*)(tile + k*64 + cj);
                acc[0][0] = fma2(A0, bb.x, acc[0][0]);
                acc[0][1] = fma2(A0, bb.y, acc[0][1]);
                acc[1][0] = fma2(A1, bb.x, acc[1][0]);
                acc[1][1] = fma2(A1, bb.y, acc[1][1]);
                acc[2][0] = fma2(A2, bb.x, acc[2][0]);
                acc[2][1] = fma2(A2, bb.y, acc[2][1]);
                acc[3][0] = fma2(A3, bb.x, acc[3][0]);
                acc[3][1] = fma2(A3, bb.y, acc[3][1]);
            }
            if (tid < 64){
                #pragma unroll 8
                for (int k = 0; k < 64; k++) ssum += tile[k*64 + tid];
            }
            __syncthreads();
        }
        #pragma unroll
        for (int r = 0; r < 4; r++){
            float2 v0 = upk2(acc[r][0]);
            float2 v1 = upk2(acc[r][1]);
            atomicAdd(&g_G[(ri + r)*64 + cj + 0], v0.x);
            atomicAdd(&g_G[(ri + r)*64 + cj + 1], v0.y);
            atomicAdd(&g_G[(ri + r)*64 + cj + 2], v1.x);
            atomicAdd(&g_G[(ri + r)*64 + cj + 3], v1.y);
        }
        if (tid < 64) atomicAdd(&g_s[(gb >> 3)*64 + tid], ssum);
        return;
    }
    if (blk < 520){
        // ---- wfrag: blocks 512..519 build weight A-fragments ----
        int unit = (blk - 512)*256 + tid;     // 0..2047
        int lane = unit & 31, ks = (unit >> 5) & 3, ng = unit >> 7;
        int n  = ng*16 + (lane >> 2);
        int k  = ks*16 + 2*(lane & 3);
        float w_k_n   = W1[k*D + n],        w_k1_n  = W1[(k+1)*D + n];
        float w_k_n8  = W1[k*D + n + 8],    w_k1_n8 = W1[(k+1)*D + n + 8];
        float w_k8_n  = W1[(k+8)*D + n],    w_k9_n  = W1[(k+9)*D + n];
        float w_k8_n8 = W1[(k+8)*D + n + 8],w_k9_n8 = W1[(k+9)*D + n + 8];
        uint4 H, L;
        H.x = (u32)bf16hi_us(w_k_n)   | ((u32)bf16hi_us(w_k1_n)  << 16);
        H.y = (u32)bf16hi_us(w_k_n8)  | ((u32)bf16hi_us(w_k1_n8) << 16);
        H.z = (u32)bf16hi_us(w_k8_n)  | ((u32)bf16hi_us(w_k9_n)  << 16);
        H.w = (u32)bf16hi_us(w_k8_n8) | ((u32)bf16hi_us(w_k9_n8) << 16);
        L.x = (u32)bf16lo_us(w_k_n)   | ((u32)bf16lo_us(w_k1_n)  << 16);
        L.y = (u32)bf16lo_us(w_k_n8)  | ((u32)bf16lo_us(w_k1_n8) << 16);
        L.z = (u32)bf16lo_us(w_k8_n)  | ((u32)bf16lo_us(w_k9_n)  << 16);
        L.w = (u32)bf16lo_us(w_k8_n8) | ((u32)bf16lo_us(w_k9_n8) << 16);
        g_WfragH[unit] = H;
        g_WfragL[unit] = L;
        return;
    }
    // ---- pool: blocks 520..2567; 64 rows each, atomic partial sums ----
    {
        int pb = blk - 520;                   // 0..2047
        int b = pb >> 5, sub = pb & 31;       // rows [sub*64, sub*64+64)
        int c4 = tid & 63, rg = tid >> 6;
        const ulonglong2* p = (const ulonglong2*)(x + ((size_t)(b*NPG + sub*64 + rg))*D) + c4;
        u64 s01 = 0ull, s23 = 0ull;
        #pragma unroll 16
        for (int k = 0; k < 16; k++){
            ulonglong2 v = p[(size_t)k*256];  // stride 4 rows
            s01 = add2(s01, v.x);
            s23 = add2(s23, v.y);
        }
        ulonglong2* sp = (ulonglong2*)tile;
        sp[tid] = make_ulonglong2(s01, s23);
        __syncthreads();
        if (tid < 64){
            ulonglong2 a = sp[tid], b2v = sp[tid+64], c = sp[tid+128], d = sp[tid+192];
            u64 t01 = add2(add2(a.x, b2v.x), add2(c.x, d.x));
            u64 t23 = add2(add2(a.y, b2v.y), add2(c.y, d.y));
            float2 f01 = upk2(t01), f23 = upk2(t23);
            float t = (f01.x + f01.y) + (f23.x + f23.y);
            t += __shfl_down_sync(0xffffffffu, t, 4, 8);
            t += __shfl_down_sync(0xffffffffu, t, 2, 8);
            t += __shfl_down_sync(0xffffffffu, t, 1, 8);
            if ((tid & 7) == 0)
                atomicAdd(&g_pooled[b*128 + (sub >> 1)*8 + (tid >> 3)], t * (1.0f/4096.0f));
        }
    }
}

// ================= K1: stats — block=j, 128 threads (t=graph, h=half) =================
__global__ void __launch_bounds__(128) stats_kernel(const float* __restrict__ W1,
                                                    const float* __restrict__ b1,
                                                    const float* __restrict__ gamma,
                                                    const float* __restrict__ beta){
    __shared__ float wcol[64], wb[128];
    __shared__ float uh[2][64], sgwh[2][64], csh[2][64];
    __shared__ float rs0[4], rs1[4], rs2[4];
    int j = blockIdx.x;
    int tid = threadIdx.x, t = tid & 63, h = tid >> 6;

    if (h == 0) wcol[t] = W1[t*D + j];
    wb[tid] = W1[(64 + tid)*D + j];
    __syncthreads();

    float cs = 0.0f;
    #pragma unroll 8
    for (int s = 0; s < 32; s++) cs += wcol[h*32 + s] * g_G[(h*32 + s)*64 + t];
    csh[h][t] = cs;
    float up = (h == 0) ? b1[j] : 0.0f;
    const float4* pp = (const float4*)(g_pooled + t*128 + h*64);
    #pragma unroll 8
    for (int k4 = 0; k4 < 16; k4++){
        float4 p = pp[k4];
        int kb = h*64 + k4*4;
        up += p.x*wb[kb] + p.y*wb[kb+1] + p.z*wb[kb+2] + p.w*wb[kb+3];
    }
    uh[h][t] = up;
    float sp = 0.0f;
    const float4* spt = (const float4*)(g_s + t*64 + h*32);
    #pragma unroll 4
    for (int k4 = 0; k4 < 8; k4++){
        float4 p = spt[k4];
        int kb = h*32 + k4*4;
        sp += p.x*wcol[kb] + p.y*wcol[kb+1] + p.z*wcol[kb+2] + p.w*wcol[kb+3];
    }
    sgwh[h][t] = sp;
    __syncthreads();

    float r0 = 0.0f, r1 = 0.0f, r2 = 0.0f;
    if (h == 0){
        float u   = uh[0][t] + uh[1][t];
        g_u[t*D + j] = u;
        float sgw = sgwh[0][t] + sgwh[1][t];
        float cst = csh[0][t] + csh[1][t];
        r0 = sgw + 2048.0f*u;
        r1 = 2.0f*u*sgw + 2048.0f*u*u;
        r2 = cst * wcol[t];
    }
    #pragma unroll
    for (int o = 16; o > 0; o >>= 1){
        r0 += __shfl_down_sync(0xffffffffu, r0, o);
        r1 += __shfl_down_sync(0xffffffffu, r1, o);
        r2 += __shfl_down_sync(0xffffffffu, r2, o);
    }
    int wid = tid >> 5, lane = tid & 31;
    if (lane == 0){ rs0[wid] = r0; rs1[wid] = r1; rs2[wid] = r2; }
    __syncthreads();
    if (tid == 0){
        const float invN = 1.0f / (float)NTOT;
        float mean  = (rs0[0] + rs0[1]) * invN;
        float sumsq = (rs2[0] + rs2[1]) + (rs1[0] + rs1[1]);
        float var   = sumsq * invN - mean*mean;
        float a = gamma[j] * rsqrtf(var + 1e-5f);
        g_a[j] = a;
        g_c[j] = beta[j] - mean*a;
    }
}

// ================= K2: fused main — weight-stationary MMA, packed tanh-GELU epilogue =================
__global__ void __launch_bounds__(256, 3) main_kernel(const float* __restrict__ cond,
                                                      const float* __restrict__ W2,
                                                      const float* __restrict__ b2,
                                                      float* __restrict__ out){
    uint4* sF  = (uint4*)dsm;              // [chunk8][ks4][lane32] = 16 KB
    uint4* sWH = (uint4*)(dsm + 4096);     // ks 2,3 weight frags, 16 KB
    uint4* sWL = (uint4*)(dsm + 8192);     // 16 KB
    float* sa  = dsm + 12288;              // 256
    float* sfc = sa + 256;                 // 256
    float* sw2 = sfc + 256;                // 768
    float* sprt= sw2 + 768;                // [8][64][3] = 1536

    int tid = threadIdx.x, w = tid >> 5, l = tid & 31;
    int row0 = blockIdx.x * 64;
    int g = blockIdx.x >> 5;

    // re-zero atomic accumulators for next replay
    // g_G: 1024 float4, g_s: 1024 float4, g_pooled: 2048 float4
    if (blockIdx.x == 0){
        float4 z = make_float4(0,0,0,0);
        #pragma unroll
        for (int i = 0; i < 4; i++) ((float4*)g_G)[tid + i*256] = z;
    } else if (blockIdx.x == 1){
        float4 z = make_float4(0,0,0,0);
        #pragma unroll
        for (int i = 0; i < 4; i++) ((float4*)g_s)[tid + i*256] = z;
    } else if (blockIdx.x == 2){
        float4 z = make_float4(0,0,0,0);
        #pragma unroll
        for (int i = 0; i < 4; i++) ((float4*)g_pooled)[tid + i*256] = z;
    } else if (blockIdx.x == 3){
        float4 z = make_float4(0,0,0,0);
        #pragma unroll
        for (int i = 0; i < 4; i++) ((float4*)g_pooled)[1024 + tid + i*256] = z;
    }

    {
        float a = g_a[tid];
        sa[tid]  = a;
        sfc[tid] = fmaf(g_u[g*D + tid], a, g_c[tid]);
    }
    for (int i = tid; i < 768; i += 256) sw2[i] = W2[i];

    uint4 AH[2][2], AL[2][2];
    #pragma unroll
    for (int nt2 = 0; nt2 < 2; nt2++)
        #pragma unroll
        for (int ks = 0; ks < 2; ks++){
            int idx = ((w*2 + nt2)*4 + ks)*32 + l;
            AH[nt2][ks] = g_WfragH[idx];
            AL[nt2][ks] = g_WfragL[idx];
        }
    #pragma unroll
    for (int i = 0; i < 4; i++){
        int u = tid + i*256;
        int lane = u & 31, ks2 = (u >> 5) & 1, ng = u >> 6;
        int src = (ng*4 + 2 + ks2)*32 + lane;
        sWH[u] = g_WfragH[src];
        sWL[u] = g_WfragL[src];
    }

    #pragma unroll
    for (int i = 0; i < 4; i++){
        int u = tid + i*256;
        int lane = u & 31, ks = (u >> 5) & 3, chunk = u >> 7;
        int mrow = row0 + chunk*8 + (lane >> 2);
        int k0 = ks*16 + 2*(lane & 3);
        const float* cp = cond + (size_t)mrow*COND + k0;
        float2 v01 = *(const float2*)cp;
        float2 v89 = *(const float2*)(cp + 8);
        u32 bh0, bl0, bh1, bl1;
        cvt_hl(v01, bh0, bl0);
        cvt_hl(v89, bh1, bl1);
        sF[u] = make_uint4(bh0, bh1, bl0, bl1);
    }
    __syncthreads();

    u64 ca2[2], cc2[2], cw2[2][3];
    #pragma unroll
    for (int nt2 = 0; nt2 < 2; nt2++){
        int n0 = w*32 + nt2*16 + (l >> 2);
        ca2[nt2] = pk2(sa[n0], sa[n0 + 8]);
        cc2[nt2] = pk2(sfc[n0], sfc[n0 + 8]);
        #pragma unroll
        for (int j = 0; j < 3; j++)
            cw2[nt2][j] = pk2(sw2[n0*3 + j], sw2[(n0+8)*3 + j]);
    }

    #pragma unroll 2
    for (int chunk = 0; chunk < 8; chunk++){
        float acc[2][4] = {{0,0,0,0},{0,0,0,0}};
        #pragma unroll
        for (int ks = 0; ks < 4; ks++){
            uint4 f = sF[(chunk*4 + ks)*32 + l];
            #pragma unroll
            for (int nt2 = 0; nt2 < 2; nt2++){
                uint4 wh, wl;
                if (ks < 2){ wh = AH[nt2][ks]; wl = AL[nt2][ks]; }
                else {
                    int idx = ((w*2 + nt2)*2 + (ks - 2))*32 + l;
                    wh = sWH[idx]; wl = sWL[idx];
                }
                mma16816(acc[nt2], (const u32*)&wh, f.x, f.y);
                mma16816(acc[nt2], (const u32*)&wh, f.z, f.w);
                mma16816(acc[nt2], (const u32*)&wl, f.x, f.y);
            }
        }
        u64 poc[3] = {0,0,0}, pod[3] = {0,0,0};
        #pragma unroll
        for (int nt2 = 0; nt2 < 2; nt2++){
            #pragma unroll
            for (int q = 0; q < 2; q++){
                u64 v2 = pk2(acc[nt2][q], acc[nt2][q + 2]);
                u64 y2 = fma2(v2, ca2[nt2], cc2[nt2]);
                u64 g2 = gelu2t(y2);
                u64* po = q ? pod : poc;
                po[0] = fma2(g2, cw2[nt2][0], po[0]);
                po[1] = fma2(g2, cw2[nt2][1], po[1]);
                po[2] = fma2(g2, cw2[nt2][2], po[2]);
            }
        }
        float oc[3], od[3];
        #pragma unroll
        for (int j = 0; j < 3; j++){
            float2 a = upk2(poc[j]); oc[j] = a.x + a.y;
            float2 b = upk2(pod[j]); od[j] = b.x + b.y;
        }
        #pragma unroll
        for (int j = 0; j < 3; j++){
            #pragma unroll
            for (int o = 4; o < 32; o <<= 1){
                oc[j] += __shfl_xor_sync(0xffffffffu, oc[j], o);
                od[j] += __shfl_xor_sync(0xffffffffu, od[j], o);
            }
        }
        if (l < 4){
            int r0 = chunk*8 + 2*l;
            #pragma unroll
            for (int j = 0; j < 3; j++){
                sprt[(w*64 + r0    )*3 + j] = oc[j];
                sprt[(w*64 + r0 + 1)*3 + j] = od[j];
            }
        }
    }
    __syncthreads();

    if (tid < 192){
        float s = b2[tid % 3];
        #pragma unroll
        for (int wi = 0; wi < 8; wi++) s += sprt[wi*192 + tid];
        out[(size_t)row0*3 + tid] = s;
    }
}

// ================= launch =================
extern "C" void kernel_launch(void* const* d_in, const int* in_sizes, int n_in,
                              void* d_out, int out_size){
    const float* x     = (const float*)d_in[0];
    const float* cond  = (const float*)d_in[2];
    const float* W1    = (const float*)d_in[3];
    const float* b1    = (const float*)d_in[4];
    const float* gamma = (const float*)d_in[5];
    const float* beta  = (const float*)d_in[6];
    const float* W2    = (const float*)d_in[7];
    const float* b2    = (const float*)d_in[8];
    float* out = (float*)d_out;

    static int configured = 0;
    if (!configured){
        cudaFuncSetAttribute(main_kernel, cudaFuncAttributeMaxDynamicSharedMemorySize, 60416);
        configured = 1;
    }

    prep_kernel <<<2568, 256>>>(x, cond, W1);
    stats_kernel<<<256,  128>>>(W1, b1, gamma, beta);
    main_kernel <<<2048, 256, 60416>>>(cond, W2, b2, out);
}

// round 17
// speedup vs baseline: 1.3204x; 1.3204x over previous
#include <cuda_runtime.h>
#include <cuda_bf16.h>

#define NTOT (64*2048)
#define D    256
#define COND 64
#define NG   64
#define NPG  2048

typedef unsigned long long u64;
typedef unsigned int u32;

// ---------------- device scratch ----------------
__device__ float g_pooled[NG*128];    // atomic-accumulated (zeroed by main each run)
__device__ float g_u[NG*D];
__device__ float g_G[COND*COND];      // atomic-accumulated Gram (zeroed by main each run)
__device__ float g_s[NG*COND];        // atomic-accumulated per-graph col sums
__device__ float g_a[D];
__device__ float g_c[D];
__device__ uint4 g_WfragH[2048];
__device__ uint4 g_WfragL[2048];

extern __shared__ float dsm[];

// ---------------- f32x2 + misc helpers ----------------
__device__ __forceinline__ u64 fma2(u64 a, u64 b, u64 c){
    u64 d; asm("fma.rn.f32x2 %0, %1, %2, %3;" : "=l"(d) : "l"(a), "l"(b), "l"(c)); return d;
}
__device__ __forceinline__ u64 mul2(u64 a, u64 b){
    u64 d; asm("mul.rn.f32x2 %0, %1, %2;" : "=l"(d) : "l"(a), "l"(b)); return d;
}
__device__ __forceinline__ u64 add2(u64 a, u64 b){
    u64 d; asm("add.rn.f32x2 %0, %1, %2;" : "=l"(d) : "l"(a), "l"(b)); return d;
}
__device__ __forceinline__ u64 dup2(float v){
    u64 r; asm("mov.b64 %0, {%1, %1};" : "=l"(r) : "f"(v)); return r;
}
__device__ __forceinline__ u64 pk2(float x, float y){
    u64 r; asm("mov.b64 %0, {%1, %2};" : "=l"(r) : "f"(x), "f"(y)); return r;
}
__device__ __forceinline__ float2 upk2(u64 v){
    float2 f; asm("mov.b64 {%0, %1}, %2;" : "=f"(f.x), "=f"(f.y) : "l"(v)); return f;
}
__device__ __forceinline__ u32 smem_u32(const void* p){
    u32 a;
    asm("{ .reg .u64 t; cvta.to.shared.u64 t, %1; cvt.u32.u64 %0, t; }" : "=r"(a) : "l"(p));
    return a;
}
__device__ __forceinline__ void cpasync16(u32 saddr, const void* gaddr){
    asm volatile("cp.async.cg.shared.global [%0], [%1], 16;" :: "r"(saddr), "l"(gaddr) : "memory");
}
#define CP_COMMIT() asm volatile("cp.async.commit_group;" ::: "memory")
#define CP_WAIT(n)  asm volatile("cp.async.wait_group %0;" :: "n"(n) : "memory")

__device__ __forceinline__ unsigned short bf16hi_us(float w){
    return __bfloat16_as_ushort(__float2bfloat16(w));
}
__device__ __forceinline__ unsigned short bf16lo_us(float w){
    float r = w - __bfloat162float(__float2bfloat16(w));
    return __bfloat16_as_ushort(__float2bfloat16(r));
}
__device__ __forceinline__ void cvt_hl(float2 v, u32& hi, u32& lo){
    __nv_bfloat162 h = __float22bfloat162_rn(v);
    float2 hf = __bfloat1622float2(h);
    __nv_bfloat162 l2 = __float22bfloat162_rn(make_float2(v.x - hf.x, v.y - hf.y));
    hi = *reinterpret_cast<u32*>(&h);
    lo = *reinterpret_cast<u32*>(&l2);
}
__device__ __forceinline__ void mma16816(float* c, const u32* a, u32 b0, u32 b1){
    asm("mma.sync.aligned.m16n8k16.row.col.f32.bf16.bf16.f32 "
        "{%0,%1,%2,%3}, {%4,%5,%6,%7}, {%8,%9}, {%0,%1,%2,%3};"
        : "+f"(c[0]), "+f"(c[1]), "+f"(c[2]), "+f"(c[3])
        : "r"(a[0]), "r"(a[1]), "r"(a[2]), "r"(a[3]), "r"(b0), "r"(b1));
}

// Packed tanh-form GELU using MUFU.TANH
__device__ __forceinline__ u64 gelu2t(u64 y2){
    u64 xx    = mul2(y2, y2);
    u64 inner = fma2(xx, dup2(0.044715f), dup2(1.0f));
    u64 arg   = mul2(mul2(y2, inner), dup2(0.79788456080286536f));
    float2 av = upk2(arg);
    float t0, t1;
    asm("tanh.approx.f32 %0, %1;" : "=f"(t0) : "f"(av.x));
    asm("tanh.approx.f32 %0, %1;" : "=f"(t1) : "f"(av.y));
    u64 half = fma2(pk2(t0, t1), dup2(0.5f), dup2(0.5f));
    return mul2(y2, half);
}

// ================= K0: prep — gram(0..511) + wfrag(512..519) + pool(520..2567) =================
// 16 KB static smem. LPT: long gram blocks first. Pool uses cp.async double-buffering.
__global__ void __launch_bounds__(256) prep_kernel(const float* __restrict__ x,
                                                   const float* __restrict__ cond,
                                                   const float* __restrict__ W1){
    __shared__ float tile[4096];   // 16 KB (gram tile / pool 2x8KB buffers)
    int blk = blockIdx.x, tid = threadIdx.x;

    if (blk < 512){
        // ---- gram: 512 blocks x 256 rows (4 sub-tiles of 64), atomics into g_G / g_s ----
        int gb = blk;
        int ti = tid >> 4, tj = tid & 15;
        int ri = ti*4, cj = tj*4;
        u64 acc[4][2];
        #pragma unroll
        for (int r = 0; r < 4; r++){ acc[r][0] = 0ull; acc[r][1] = 0ull; }
        float ssum = 0.0f;

        for (int sub = 0; sub < 4; sub++){
            size_t base = ((size_t)gb*256 + sub*64) * COND;
            for (int i = tid; i < 4096; i += 256) tile[i] = cond[base + i];
            __syncthreads();
            #pragma unroll 4
            for (int k = 0; k < 64; k++){
                float4 av = *(const float4*)(tile + k*64 + ri);
                u64 A0 = dup2(av.x), A1 = dup2(av.y), A2 = dup2(av.z), A3 = dup2(av.w);
                ulonglong2 bb = *(const ulonglong2*)(tile + k*64 + cj);
                acc[0][0] = fma2(A0, bb.x, acc[0][0]);
                acc[0][1] = fma2(A0, bb.y, acc[0][1]);
                acc[1][0] = fma2(A1, bb.x, acc[1][0]);
                acc[1][1] = fma2(A1, bb.y, acc[1][1]);
                acc[2][0] = fma2(A2, bb.x, acc[2][0]);
                acc[2][1] = fma2(A2, bb.y, acc[2][1]);
                acc[3][0] = fma2(A3, bb.x, acc[3][0]);
                acc[3][1] = fma2(A3, bb.y, acc[3][1]);
            }
            if (tid < 64){
                #pragma unroll 8
                for (int k = 0; k < 64; k++) ssum += tile[k*64 + tid];
            }
            __syncthreads();
        }
        #pragma unroll
        for (int r = 0; r < 4; r++){
            float2 v0 = upk2(acc[r][0]);
            float2 v1 = upk2(acc[r][1]);
            atomicAdd(&g_G[(ri + r)*64 + cj + 0], v0.x);
            atomicAdd(&g_G[(ri + r)*64 + cj + 1], v0.y);
            atomicAdd(&g_G[(ri + r)*64 + cj + 2], v1.x);
            atomicAdd(&g_G[(ri + r)*64 + cj + 3], v1.y);
        }
        if (tid < 64) atomicAdd(&g_s[(gb >> 3)*64 + tid], ssum);
        return;
    }
    if (blk < 520){
        // ---- wfrag: blocks 512..519 build weight A-fragments ----
        int unit = (blk - 512)*256 + tid;     // 0..2047
        int lane = unit & 31, ks = (unit >> 5) & 3, ng = unit >> 7;
        int n  = ng*16 + (lane >> 2);
        int k  = ks*16 + 2*(lane & 3);
        float w_k_n   = W1[k*D + n],        w_k1_n  = W1[(k+1)*D + n];
        float w_k_n8  = W1[k*D + n + 8],    w_k1_n8 = W1[(k+1)*D + n + 8];
        float w_k8_n  = W1[(k+8)*D + n],    w_k9_n  = W1[(k+9)*D + n];
        float w_k8_n8 = W1[(k+8)*D + n + 8],w_k9_n8 = W1[(k+9)*D + n + 8];
        uint4 H, L;
        H.x = (u32)bf16hi_us(w_k_n)   | ((u32)bf16hi_us(w_k1_n)  << 16);
        H.y = (u32)bf16hi_us(w_k_n8)  | ((u32)bf16hi_us(w_k1_n8) << 16);
        H.z = (u32)bf16hi_us(w_k8_n)  | ((u32)bf16hi_us(w_k9_n)  << 16);
        H.w = (u32)bf16hi_us(w_k8_n8) | ((u32)bf16hi_us(w_k9_n8) << 16);
        L.x = (u32)bf16lo_us(w_k_n)   | ((u32)bf16lo_us(w_k1_n)  << 16);
        L.y = (u32)bf16lo_us(w_k_n8)  | ((u32)bf16lo_us(w_k1_n8) << 16);
        L.z = (u32)bf16lo_us(w_k8_n)  | ((u32)bf16lo_us(w_k9_n)  << 16);
        L.w = (u32)bf16lo_us(w_k8_n8) | ((u32)bf16lo_us(w_k9_n8) << 16);
        g_WfragH[unit] = H;
        g_WfragL[unit] = L;
        return;
    }
    // ---- pool: blocks 520..2567; 64 rows each via cp.async 2x8KB double-buffer ----
    {
        int pb = blk - 520;                   // 0..2047
        int b = pb >> 5, sub = pb & 31;       // rows [sub*64, sub*64+64)
        const float* gb = x + ((size_t)(b*NPG + sub*64))*D;
        u32 s0 = smem_u32(tile);

        int slot1 = tid, slot2 = tid + 256;   // 512 slots of 16B per 8-row buffer
        int r1 = slot1 >> 6, c1 = (slot1 & 63)*4;
        int r2 = slot2 >> 6, c2 = (slot2 & 63)*4;
        const float* g1 = gb + r1*D + c1;
        const float* g2 = gb + r2*D + c2;
        u32 sa1 = s0 + slot1*16;
        u32 sa2 = s0 + slot2*16;

        // prologue: chunk 0 -> buffer 0
        cpasync16(sa1, g1);
        cpasync16(sa2, g2);
        CP_COMMIT();

        u64 s01 = 0ull, s23 = 0ull;
        #pragma unroll
        for (int c = 0; c < 8; c++){
            if (c + 1 < 8){
                int nb = (c + 1) & 1;
                cpasync16(sa1 + nb*8192, g1 + (c+1)*8*D);
                cpasync16(sa2 + nb*8192, g2 + (c+1)*8*D);
                CP_COMMIT();
                CP_WAIT(1);
            } else {
                CP_WAIT(0);
            }
            int buf = c & 1;
            ulonglong2 v1 = *(const ulonglong2*)((const char*)tile + buf*8192 + slot1*16);
            ulonglong2 v2 = *(const ulonglong2*)((const char*)tile + buf*8192 + slot2*16);
            s01 = add2(s01, v1.x); s23 = add2(s23, v1.y);
            s01 = add2(s01, v2.x); s23 = add2(s23, v2.y);
        }

        ulonglong2* sp = (ulonglong2*)tile;
        sp[tid] = make_ulonglong2(s01, s23);   // own slot, no race with own reads
        __syncthreads();
        if (tid < 64){
            ulonglong2 a = sp[tid], b2v = sp[tid+64], cc = sp[tid+128], d = sp[tid+192];
            u64 t01 = add2(add2(a.x, b2v.x), add2(cc.x, d.x));
            u64 t23 = add2(add2(a.y, b2v.y), add2(cc.y, d.y));
            float2 f01 = upk2(t01), f23 = upk2(t23);
            float t = (f01.x + f01.y) + (f23.x + f23.y);
            t += __shfl_down_sync(0xffffffffu, t, 4, 8);
            t += __shfl_down_sync(0xffffffffu, t, 2, 8);
            t += __shfl_down_sync(0xffffffffu, t, 1, 8);
            if ((tid & 7) == 0)
                atomicAdd(&g_pooled[b*128 + (sub >> 1)*8 + (tid >> 3)], t * (1.0f/4096.0f));
        }
    }
}

// ================= K1: stats — block=j, 128 threads (t=graph, h=half) =================
__global__ void __launch_bounds__(128) stats_kernel(const float* __restrict__ W1,
                                                    const float* __restrict__ b1,
                                                    const float* __restrict__ gamma,
                                                    const float* __restrict__ beta){
    __shared__ float wcol[64], wb[128];
    __shared__ float uh[2][64], sgwh[2][64], csh[2][64];
    __shared__ float rs0[4], rs1[4], rs2[4];
    int j = blockIdx.x;
    int tid = threadIdx.x, t = tid & 63, h = tid >> 6;

    if (h == 0) wcol[t] = W1[t*D + j];
    wb[tid] = W1[(64 + tid)*D + j];
    __syncthreads();

    float cs = 0.0f;
    #pragma unroll 8
    for (int s = 0; s < 32; s++) cs += wcol[h*32 + s] * g_G[(h*32 + s)*64 + t];
    csh[h][t] = cs;
    float up = (h == 0) ? b1[j] : 0.0f;
    const float4* pp = (const float4*)(g_pooled + t*128 + h*64);
    #pragma unroll 8
    for (int k4 = 0; k4 < 16; k4++){
        float4 p = pp[k4];
        int kb = h*64 + k4*4;
        up += p.x*wb[kb] + p.y*wb[kb+1] + p.z*wb[kb+2] + p.w*wb[kb+3];
    }
    uh[h][t] = up;
    float sp = 0.0f;
    const float4* spt = (const float4*)(g_s + t*64 + h*32);
    #pragma unroll 4
    for (int k4 = 0; k4 < 8; k4++){
        float4 p = spt[k4];
        int kb = h*32 + k4*4;
        sp += p.x*wcol[kb] + p.y*wcol[kb+1] + p.z*wcol[kb+2] + p.w*wcol[kb+3];
    }
    sgwh[h][t] = sp;
    __syncthreads();

    float r0 = 0.0f, r1 = 0.0f, r2 = 0.0f;
    if (h == 0){
        float u   = uh[0][t] + uh[1][t];
        g_u[t*D + j] = u;
        float sgw = sgwh[0][t] + sgwh[1][t];
        float cst = csh[0][t] + csh[1][t];
        r0 = sgw + 2048.0f*u;
        r1 = 2.0f*u*sgw + 2048.0f*u*u;
        r2 = cst * wcol[t];
    }
    #pragma unroll
    for (int o = 16; o > 0; o >>= 1){
        r0 += __shfl_down_sync(0xffffffffu, r0, o);
        r1 += __shfl_down_sync(0xffffffffu, r1, o);
        r2 += __shfl_down_sync(0xffffffffu, r2, o);
    }
    int wid = tid >> 5, lane = tid & 31;
    if (lane == 0){ rs0[wid] = r0; rs1[wid] = r1; rs2[wid] = r2; }
    __syncthreads();
    if (tid == 0){
        const float invN = 1.0f / (float)NTOT;
        float mean  = (rs0[0] + rs0[1]) * invN;
        float sumsq = (rs2[0] + rs2[1]) + (rs1[0] + rs1[1]);
        float var   = sumsq * invN - mean*mean;
        float a = gamma[j] * rsqrtf(var + 1e-5f);
        g_a[j] = a;
        g_c[j] = beta[j] - mean*a;
    }
}

// ================= K2: fused main — weight-stationary MMA, packed tanh-GELU epilogue =================
__global__ void __launch_bounds__(256, 3) main_kernel(const float* __restrict__ cond,
                                                      const float* __restrict__ W2,
                                                      const float* __restrict__ b2,
                                                      float* __restrict__ out){
    uint4* sF  = (uint4*)dsm;              // [chunk8][ks4][lane32] = 16 KB
    uint4* sWH = (uint4*)(dsm + 4096);     // ks 2,3 weight frags, 16 KB
    uint4* sWL = (uint4*)(dsm + 8192);     // 16 KB
    float* sa  = dsm + 12288;              // 256
    float* sfc = sa + 256;                 // 256
    float* sw2 = sfc + 256;                // 768
    float* sprt= sw2 + 768;                // [8][64][3] = 1536

    int tid = threadIdx.x, w = tid >> 5, l = tid & 31;
    int row0 = blockIdx.x * 64;
    int g = blockIdx.x >> 5;

    // re-zero atomic accumulators for next replay
    // g_G: 1024 float4, g_s: 1024 float4, g_pooled: 2048 float4
    if (blockIdx.x == 0){
        float4 z = make_float4(0,0,0,0);
        #pragma unroll
        for (int i = 0; i < 4; i++) ((float4*)g_G)[tid + i*256] = z;
    } else if (blockIdx.x == 1){
        float4 z = make_float4(0,0,0,0);
        #pragma unroll
        for (int i = 0; i < 4; i++) ((float4*)g_s)[tid + i*256] = z;
    } else if (blockIdx.x == 2){
        float4 z = make_float4(0,0,0,0);
        #pragma unroll
        for (int i = 0; i < 4; i++) ((float4*)g_pooled)[tid + i*256] = z;
    } else if (blockIdx.x == 3){
        float4 z = make_float4(0,0,0,0);
        #pragma unroll
        for (int i = 0; i < 4; i++) ((float4*)g_pooled)[1024 + tid + i*256] = z;
    }

    {
        float a = g_a[tid];
        sa[tid]  = a;
        sfc[tid] = fmaf(g_u[g*D + tid], a, g_c[tid]);
    }
    for (int i = tid; i < 768; i += 256) sw2[i] = W2[i];

    uint4 AH[2][2], AL[2][2];
    #pragma unroll
    for (int nt2 = 0; nt2 < 2; nt2++)
        #pragma unroll
        for (int ks = 0; ks < 2; ks++){
            int idx = ((w*2 + nt2)*4 + ks)*32 + l;
            AH[nt2][ks] = g_WfragH[idx];
            AL[nt2][ks] = g_WfragL[idx];
        }
    #pragma unroll
    for (int i = 0; i < 4; i++){
        int u = tid + i*256;
        int lane = u & 31, ks2 = (u >> 5) & 1, ng = u >> 6;
        int src = (ng*4 + 2 + ks2)*32 + lane;
        sWH[u] = g_WfragH[src];
        sWL[u] = g_WfragL[src];
    }

    #pragma unroll
    for (int i = 0; i < 4; i++){
        int u = tid + i*256;
        int lane = u & 31, ks = (u >> 5) & 3, chunk = u >> 7;
        int mrow = row0 + chunk*8 + (lane >> 2);
        int k0 = ks*16 + 2*(lane & 3);
        const float* cp = cond + (size_t)mrow*COND + k0;
        float2 v01 = *(const float2*)cp;
        float2 v89 = *(const float2*)(cp + 8);
        u32 bh0, bl0, bh1, bl1;
        cvt_hl(v01, bh0, bl0);
        cvt_hl(v89, bh1, bl1);
        sF[u] = make_uint4(bh0, bh1, bl0, bl1);
    }
    __syncthreads();

    u64 ca2[2], cc2[2], cw2[2][3];
    #pragma unroll
    for (int nt2 = 0; nt2 < 2; nt2++){
        int n0 = w*32 + nt2*16 + (l >> 2);
        ca2[nt2] = pk2(sa[n0], sa[n0 + 8]);
        cc2[nt2] = pk2(sfc[n0], sfc[n0 + 8]);
        #pragma unroll
        for (int j = 0; j < 3; j++)
            cw2[nt2][j] = pk2(sw2[n0*3 + j], sw2[(n0+8)*3 + j]);
    }

    #pragma unroll 1
    for (int chunk = 0; chunk < 8; chunk++){
        float acc[2][4] = {{0,0,0,0},{0,0,0,0}};
        #pragma unroll
        for (int ks = 0; ks < 4; ks++){
            uint4 f = sF[(chunk*4 + ks)*32 + l];
            #pragma unroll
            for (int nt2 = 0; nt2 < 2; nt2++){
                uint4 wh, wl;
                if (ks < 2){ wh = AH[nt2][ks]; wl = AL[nt2][ks]; }
                else {
                    int idx = ((w*2 + nt2)*2 + (ks - 2))*32 + l;
                    wh = sWH[idx]; wl = sWL[idx];
                }
                mma16816(acc[nt2], (const u32*)&wh, f.x, f.y);
                mma16816(acc[nt2], (const u32*)&wh, f.z, f.w);
                mma16816(acc[nt2], (const u32*)&wl, f.x, f.y);
            }
        }
        u64 poc[3] = {0,0,0}, pod[3] = {0,0,0};
        #pragma unroll
        for (int nt2 = 0; nt2 < 2; nt2++){
            #pragma unroll
            for (int q = 0; q < 2; q++){
                u64 v2 = pk2(acc[nt2][q], acc[nt2][q + 2]);
                u64 y2 = fma2(v2, ca2[nt2], cc2[nt2]);
                u64 g2 = gelu2t(y2);
                u64* po = q ? pod : poc;
                po[0] = fma2(g2, cw2[nt2][0], po[0]);
                po[1] = fma2(g2, cw2[nt2][1], po[1]);
                po[2] = fma2(g2, cw2[nt2][2], po[2]);
            }
        }
        float oc[3], od[3];
        #pragma unroll
        for (int j = 0; j < 3; j++){
            float2 a = upk2(poc[j]); oc[j] = a.x + a.y;
            float2 b = upk2(pod[j]); od[j] = b.x + b.y;
        }
        #pragma unroll
        for (int j = 0; j < 3; j++){
            #pragma unroll
            for (int o = 4; o < 32; o <<= 1){
                oc[j] += __shfl_xor_sync(0xffffffffu, oc[j], o);
                od[j] += __shfl_xor_sync(0xffffffffu, od[j], o);
            }
        }
        if (l < 4){
            int r0 = chunk*8 + 2*l;
            #pragma unroll
            for (int j = 0; j < 3; j++){
                sprt[(w*64 + r0    )*3 + j] = oc[j];
                sprt[(w*64 + r0 + 1)*3 + j] = od[j];
            }
        }
    }
    __syncthreads();

    if (tid < 192){
        float s = b2[tid % 3];
        #pragma unroll
        for (int wi = 0; wi < 8; wi++) s += sprt[wi*192 + tid];
        out[(size_t)row0*3 + tid] = s;
    }
}

// ================= launch =================
extern "C" void kernel_launch(void* const* d_in, const int* in_sizes, int n_in,
                              void* d_out, int out_size){
    const float* x     = (const float*)d_in[0];
    const float* cond  = (const float*)d_in[2];
    const float* W1    = (const float*)d_in[3];
    const float* b1    = (const float*)d_in[4];
    const float* gamma = (const float*)d_in[5];
    const float* beta  = (const float*)d_in[6];
    const float* W2    = (const float*)d_in[7];
    const float* b2    = (const float*)d_in[8];
    float* out = (float*)d_out;

    static int configured = 0;
    if (!configured){
        cudaFuncSetAttribute(main_kernel, cudaFuncAttributeMaxDynamicSharedMemorySize, 60416);
        configured = 1;
    }

    prep_kernel <<<2568, 256>>>(x, cond, W1);
    stats_kernel<<<256,  128>>>(W1, b1, gamma, beta);
    main_kernel <<<2048, 256, 60416>>>(cond, W2, b2, out);
}